// round 10
// baseline (speedup 1.0000x reference)
#include <cuda_runtime.h>
#include <cstdint>

#define N_TOK 131072
#define DIM   64
#define QSTG  8
#define KCB   1024

#define TM       64             // tokens per CTA (halved: 2 CTAs/SM overlap)
#define TKC      256            // codewords per SMEM chunk
#define NCHUNK   (KCB / TKC)    // 4
#define NTHREADS 128

typedef unsigned long long ull;

// ---- dynamic smem layout (floats) ----
// sBt  : 64 d-rows x 1024 B (row d holds 128 pairs (B[2p][d],B[2p+1][d]),
//        8B slot = p ^ (d>>2))                      : 16384
// sA   : [TM][66]
// sCn  : [TKC]
// redV/redI : [TM][16]
#define SBT_F    0
#define SA_ROWF  66
#define SA_F     (64 * 256)                  // 16384
#define SCN_F    (SA_F + TM * SA_ROWF)       // 16384 + 4224 = 20608
#define REDV_F   (SCN_F + TKC)               // 20864
#define REDI_F   (REDV_F + TM * 16)          // 21888
#define SMEM_FLOATS (REDI_F + TM * 16)       // 22912
#define SMEM_BYTES  (SMEM_FLOATS * 4)        // 91648 B ... wait: 22912*4 = 91648? no
// 22912 floats * 4 B = 91648 B -> too big for 2 CTAs? recheck: sBt is 16384 floats
// (64*256), sA 4224, sCn 256, red 2048 -> 22912 floats = 91648 B. That's 89.5 KB.
// Two CTAs would need 179 KB > 227 KB? OK it fits (227 KB usable), keep it.

__device__ double g_loss[QSTG];
__device__ float  g_cnorm[QSTG * KCB];

__device__ __forceinline__ void ffma2(ull& d, ull a, ull b) {
    asm("fma.rn.f32x2 %0, %1, %2, %0;" : "+l"(d) : "l"(a), "l"(b));
}
__device__ __forceinline__ ull dup2(float a) {
    ull r; unsigned u = __float_as_uint(a);
    asm("mov.b64 %0, {%1, %1};" : "=l"(r) : "r"(u));
    return r;
}
__device__ __forceinline__ float2 unpack2(ull v) {
    float2 r;
    asm("mov.b64 {%0, %1}, %2;" : "=f"(r.x), "=f"(r.y) : "l"(v));
    return r;
}

// ---------------------------------------------------------------------------
// prep: codeword squared norms + zero loss accumulators
// ---------------------------------------------------------------------------
__global__ void prep_kernel(const float* __restrict__ cb) {
    int k = blockIdx.x * blockDim.x + threadIdx.x;
    if (k < QSTG * KCB) {
        const float* p = cb + (size_t)k * DIM;
        float s0 = 0.f, s1 = 0.f, s2 = 0.f, s3 = 0.f;
#pragma unroll
        for (int d = 0; d < DIM; d += 4) {
            s0 = __fadd_rn(s0, __fmul_rn(p[d + 0], p[d + 0]));
            s1 = __fadd_rn(s1, __fmul_rn(p[d + 1], p[d + 1]));
            s2 = __fadd_rn(s2, __fmul_rn(p[d + 2], p[d + 2]));
            s3 = __fadd_rn(s3, __fmul_rn(p[d + 3], p[d + 3]));
        }
        g_cnorm[k] = __fadd_rn(__fadd_rn(s0, s1), __fadd_rn(s2, s3));
    }
    if (blockIdx.x == 0 && threadIdx.x < QSTG) g_loss[threadIdx.x] = 0.0;
}

// ---------------------------------------------------------------------------
// fused: all 8 VQ stages for one 64-token tile; 2 CTAs/SM overlap each
// other's staging/epilogue with FMA mainloops
// ---------------------------------------------------------------------------
__global__ void __launch_bounds__(NTHREADS, 2)
vq_kernel(const float* __restrict__ x, const float* __restrict__ cb,
          float* __restrict__ out) {
    extern __shared__ float sm[];
    float* sBt  = sm + SBT_F;
    float* sA   = sm + SA_F;
    float* sCn  = sm + SCN_F;
    float* redV = sm + REDV_F;
    int*   redI = (int*)(sm + REDI_F);
    __shared__ int   finIdx[TM];
    __shared__ float wsum[NTHREADS / 32];

    const int tid  = threadIdx.x;
    const int tokg = tid >> 4;    // 0..7 : 8 tokens each (64 total)
    const int cwg  = tid & 15;    // 0..15 : 8 codeword-pairs per chunk
    const int n0   = blockIdx.x * TM;

    float* out_xq  = out;
    float* out_idx = out + (size_t)N_TOK * DIM;

    // ---- load token tile once (t = tid>>1 covers 64 tokens, half-row each) ----
    {
        const int t = tid >> 1, hd = tid & 1;
        const float2* xr = (const float2*)(x + (size_t)(n0 + t) * DIM + hd * 32);
        float2* ar = (float2*)(sA + t * SA_ROWF + hd * 32);
#pragma unroll
        for (int m = 0; m < 16; ++m) ar[m] = xr[m];
    }

    for (int q = 0; q < QSTG; ++q) {
        const float* cbq = cb + (size_t)q * KCB * DIM;

        float bestv[8];
        int   besti[8];
#pragma unroll
        for (int ti = 0; ti < 8; ++ti) { bestv[ti] = 3.4e38f; besti[ti] = 0; }

        for (int ch = 0; ch < NCHUNK; ++ch) {
            const int k0 = ch * TKC;
            __syncthreads();   // previous users of sBt / sA writers done

            // ---- stage B chunk as transposed pairs, slot = p ^ (d>>2) ----
            {
                const float4* gb = (const float4*)(cbq + (size_t)k0 * DIM);
#pragma unroll
                for (int it = 0; it < 16; ++it) {
                    int L = it * NTHREADS + tid;       // 0..2047
                    int p  = L >> 4;                   // pair index 0..127
                    int dq = L & 15;                   // d quad 0..15
                    float4 v1 = gb[(2 * p) * 16 + dq];
                    float4 v2 = gb[(2 * p + 1) * 16 + dq];
                    const float* a1 = &v1.x;
                    const float* a2 = &v2.x;
                    int swz = p ^ dq;
#pragma unroll
                    for (int m = 0; m < 4; ++m) {
                        float2* dst = (float2*)((char*)sBt + (size_t)(4 * dq + m) * 1024) + swz;
                        *dst = make_float2(a1[m], a2[m]);
                    }
                }
                if (tid < TKC - NTHREADS) { }  // (no-op; TKC==2*NTHREADS below)
                sCn[tid]            = g_cnorm[q * KCB + k0 + tid];
                sCn[tid + NTHREADS] = g_cnorm[q * KCB + k0 + tid + NTHREADS];
            }
            __syncthreads();

            // ---- 8 tokens x 8 codeword-pairs register tile ----
            ull acc[64];
#pragma unroll
            for (int c = 0; c < 64; ++c) acc[c] = 0ull;

            const float* aTok = sA + tokg * 8 * SA_ROWF;
#pragma unroll 4
            for (int d = 0; d < DIM; ++d) {
                ull a2r[8];
#pragma unroll
                for (int ti = 0; ti < 8; ++ti)
                    a2r[ti] = dup2(aTok[ti * SA_ROWF + d]);
                const ull* bRow = (const ull*)((char*)sBt + (size_t)d * 1024) + (cwg ^ (d >> 2));
                ull b2r[8];
#pragma unroll
                for (int j = 0; j < 8; ++j) b2r[j] = bRow[16 * j];
#pragma unroll
                for (int ti = 0; ti < 8; ++ti)
#pragma unroll
                    for (int j = 0; j < 8; ++j)
                        ffma2(acc[ti * 8 + j], a2r[ti], b2r[j]);
            }

            // ---- running argmin: val = cnorm - 2*dot ----
#pragma unroll
            for (int j = 0; j < 8; ++j) {
                const int kl = 2 * (cwg + 16 * j);
                const float2 cn = *(const float2*)(sCn + kl);
                const int kg = k0 + kl;
#pragma unroll
                for (int ti = 0; ti < 8; ++ti) {
                    float2 p = unpack2(acc[ti * 8 + j]);
                    float v0 = fmaf(-2.0f, p.x, cn.x);
                    float v1 = fmaf(-2.0f, p.y, cn.y);
                    bool l0 = v0 < bestv[ti];
                    bestv[ti] = l0 ? v0 : bestv[ti];
                    besti[ti] = l0 ? kg : besti[ti];
                    bool l1 = v1 < bestv[ti];
                    bestv[ti] = l1 ? v1 : bestv[ti];
                    besti[ti] = l1 ? (kg + 1) : besti[ti];
                }
            }
        }
        __syncthreads();

        // ---- cross-thread argmin (16 partials per token), index tiebreak ----
#pragma unroll
        for (int ti = 0; ti < 8; ++ti) {
            int t = tokg * 8 + ti;
            redV[t * 16 + cwg] = bestv[ti];
            redI[t * 16 + cwg] = besti[ti];
        }
        __syncthreads();
        if (tid < TM) {
            const float* rv = redV + tid * 16;
            const int*   ri = redI + tid * 16;
            float bv = rv[0];
            int   bi = ri[0];
#pragma unroll
            for (int g = 1; g < 16; ++g) {
                float v  = rv[g];
                int   ii = ri[g];
                if (v < bv || (v == bv && ii < bi)) { bv = v; bi = ii; }
            }
            finIdx[tid] = bi;
            out_idx[(size_t)(n0 + tid) * QSTG + q] = (float)bi;
        }
        __syncthreads();

        // ---- residual update (in padded sA) + commitment loss ----
        {
            const int t = tid >> 1, hd = tid & 1;
            const int idx = finIdx[t];
            const float4* c4 = (const float4*)(cbq + (size_t)idx * DIM + hd * 32);
            float2* r2 = (float2*)(sA + t * SA_ROWF + hd * 32);
            float ls = 0.f;
#pragma unroll
            for (int m = 0; m < 8; ++m) {
                float4 cv = c4[m];
                float2 ra = r2[2 * m], rb = r2[2 * m + 1];
                float2 na, nb;
                na.x = __fsub_rn(ra.x, cv.x);
                na.y = __fsub_rn(ra.y, cv.y);
                nb.x = __fsub_rn(rb.x, cv.z);
                nb.y = __fsub_rn(rb.y, cv.w);
                r2[2 * m]     = na;
                r2[2 * m + 1] = nb;
                ls = fmaf(na.x, na.x, ls);
                ls = fmaf(na.y, na.y, ls);
                ls = fmaf(nb.x, nb.x, ls);
                ls = fmaf(nb.y, nb.y, ls);
            }
#pragma unroll
            for (int off = 16; off; off >>= 1)
                ls += __shfl_down_sync(0xffffffff, ls, off);
            if ((tid & 31) == 0) wsum[tid >> 5] = ls;
            __syncthreads();
            if (tid == 0) {
                float tot = 0.f;
#pragma unroll
                for (int w = 0; w < NTHREADS / 32; ++w) tot += wsum[w];
                atomicAdd(&g_loss[q], (double)tot);
            }
        }
        // next stage's top-of-chunk __syncthreads orders sA writes vs reads
    }
    __syncthreads();

    // ---- xq = x - final_residual ----
    {
        const int t = tid >> 1, hd = tid & 1;
        const float2* xr = (const float2*)(x + (size_t)(n0 + t) * DIM + hd * 32);
        const float2* rr = (const float2*)(sA + t * SA_ROWF + hd * 32);
        float2* o2 = (float2*)(out_xq + (size_t)(n0 + t) * DIM + hd * 32);
#pragma unroll
        for (int m = 0; m < 16; ++m) {
            float2 xv = xr[m], rv = rr[m], ov;
            ov.x = __fsub_rn(xv.x, rv.x);
            ov.y = __fsub_rn(xv.y, rv.y);
            o2[m] = ov;
        }
    }
}

// ---------------------------------------------------------------------------
__global__ void loss_kernel(float* __restrict__ out) {
    if (threadIdx.x < QSTG)
        out[(size_t)N_TOK * DIM + (size_t)N_TOK * QSTG + threadIdx.x] =
            (float)(g_loss[threadIdx.x] / (double)((size_t)N_TOK * DIM));
}

extern "C" void kernel_launch(void* const* d_in, const int* in_sizes, int n_in,
                              void* d_out, int out_size) {
    const float* x  = (const float*)d_in[0];
    const float* cb = (const float*)d_in[1];
    if (n_in >= 2 && in_sizes[0] == QSTG * KCB * DIM && in_sizes[1] == N_TOK * DIM) {
        const float* t = x; x = cb; cb = t;
    }
    float* out = (float*)d_out;

    cudaFuncSetAttribute(vq_kernel,
                         cudaFuncAttributeMaxDynamicSharedMemorySize, SMEM_BYTES);

    prep_kernel<<<(QSTG * KCB + 255) / 256, 256>>>(cb);
    vq_kernel<<<N_TOK / TM, NTHREADS, SMEM_BYTES>>>(x, cb, out);
    loss_kernel<<<1, 32>>>(out);
}